// round 15
// baseline (speedup 1.0000x reference)
#include <cuda_runtime.h>
#include <cuda_fp16.h>
#include <cstdint>

#define S_LEN 2048
#define DK    64
#define BH    32
#define NKT   16
#define NQT   16

// smem: K tile [128][72] fp16 (144B rows), V tile [64][136] fp16 (272B rows)
#define K_OFF 0
#define V_OFF 18432
#define SMEM_TOT (18432 + 17408)

__device__ __half g_Qf[(size_t)BH * S_LEN * DK];
__device__ __half g_Kf[(size_t)BH * S_LEN * DK];   // rows permuted within 16-groups
__device__ __half g_Vtf[(size_t)BH * DK * S_LEN];  // [bh][d][k], k permuted likewise

// slot -> original row (within a 16-group)
__device__ __forceinline__ int vperm(int o){ return ((o & 6) << 1) | ((o >> 3) << 1) | (o & 1); }
// original row -> slot (inverse)
__device__ __forceinline__ int kperm(int r){ return ((r & 2) << 2) | ((r >> 2) << 1) | (r & 1); }

// ---------------- helpers ----------------
__device__ __forceinline__ uint32_t pack_h2(float x, float y){
  __half2 t = __floats2half2_rn(x, y);
  return reinterpret_cast<uint32_t&>(t);
}

// D += A * B  (m16n8k16, fp16 in, fp32 accum)
__device__ __forceinline__ void mma_h(float d[4], const uint32_t a[4], const uint32_t b[2]){
  asm volatile("mma.sync.aligned.m16n8k16.row.col.f32.f16.f16.f32 "
    "{%0,%1,%2,%3}, {%4,%5,%6,%7}, {%8,%9}, {%0,%1,%2,%3};"
    : "+f"(d[0]), "+f"(d[1]), "+f"(d[2]), "+f"(d[3])
    : "r"(a[0]), "r"(a[1]), "r"(a[2]), "r"(a[3]), "r"(b[0]), "r"(b[1]));
}

// Copy a 128x64 fp16 tile (gmem row-major) into padded smem [128][72]. 256 threads.
__device__ __forceinline__ void copy_tile(const __half* __restrict__ src,
                                          char* sm, int off, int tid){
#pragma unroll
  for (int j = 0; j < 4; j++){
    int f = tid + j * 256;              // uint4 index, 1024 total
    int row = f >> 3, c = (f & 7);
    uint4 v = *reinterpret_cast<const uint4*>(src + (size_t)row * DK + c * 8);
    *reinterpret_cast<uint4*>(sm + off + row * 144 + c * 16) = v;
  }
}

// Load 64x128 fp16 tile (V^T, row stride S_LEN in gmem) -> smem [64][136]. 256 threads.
__device__ __forceinline__ void load_v(const __half* __restrict__ vt,
                                       char* sm, int tid){
#pragma unroll
  for (int j = 0; j < 4; j++){
    int f = tid + j * 256;              // uint4 index, 1024 total
    int row = f >> 4, c = (f & 15) << 3;
    uint4 a = *reinterpret_cast<const uint4*>(vt + (size_t)row * S_LEN + c);
    *reinterpret_cast<uint4*>(sm + V_OFF + row * 272 + c * 2) = a;
  }
}

// A fragment (m16k16) from padded smem.
__device__ __forceinline__ void lda(uint32_t a[4], const char* sm, int base,
                                    int row0, int ks, int gr, int tig){
  int off = (row0 + gr) * 144 + (ks * 16 + 2 * tig) * 2;
  a[0] = *reinterpret_cast<const uint32_t*>(sm + base + off);
  a[1] = *reinterpret_cast<const uint32_t*>(sm + base + off + 8 * 144);
  a[2] = *reinterpret_cast<const uint32_t*>(sm + base + off + 16);
  a[3] = *reinterpret_cast<const uint32_t*>(sm + base + off + 8 * 144 + 16);
}

// B fragment (k16n8, col-major): rows of smem are the n dimension.
__device__ __forceinline__ void ldb(uint32_t b[2], const char* sm, int base,
                                    int rstride, int n8, int ks, int gr, int tig){
  int off = (n8 * 8 + gr) * rstride + (ks * 16 + 2 * tig) * 2;
  b[0] = *reinterpret_cast<const uint32_t*>(sm + base + off);
  b[1] = *reinterpret_cast<const uint32_t*>(sm + base + off + 16);
}

// ---------------------------------------------------------------------------
// k0: convert Q, K (K rows permuted) and V (transposed + k-permuted) to fp16
// ---------------------------------------------------------------------------
__global__ __launch_bounds__(256) void k0_prep(
    const float* __restrict__ Qg, const float* __restrict__ Kg,
    const float* __restrict__ Vg)
{
  __shared__ float t[128][65];
  int kt = blockIdx.x, bh = blockIdx.y, tid = threadIdx.x;
  size_t base = ((size_t)bh * S_LEN + kt * 128) * DK;

#pragma unroll
  for (int i = 0; i < 4; i++){
    int f = tid + i * 256;              // 8-float segment, 1024 total
    int row = f >> 3, c0 = (f & 7) * 8;
    size_t oq = base + (size_t)row * DK + c0;
    int prow = (row & 112) | kperm(row & 15);
    size_t ok = base + (size_t)prow * DK + c0;
    const float4* qp = reinterpret_cast<const float4*>(Qg + oq);
    const float4* kp = reinterpret_cast<const float4*>(Kg + oq);
    float4 q0 = qp[0], q1 = qp[1], k0 = kp[0], k1 = kp[1];
    *reinterpret_cast<uint4*>(g_Qf + oq) =
      make_uint4(pack_h2(q0.x,q0.y), pack_h2(q0.z,q0.w),
                 pack_h2(q1.x,q1.y), pack_h2(q1.z,q1.w));
    *reinterpret_cast<uint4*>(g_Kf + ok) =
      make_uint4(pack_h2(k0.x,k0.y), pack_h2(k0.z,k0.w),
                 pack_h2(k1.x,k1.y), pack_h2(k1.z,k1.w));
  }

  // V transpose through smem, then write with permuted k (slot kd holds orig k = vperm)
  const float* Vb = Vg + base;
#pragma unroll
  for (int i = 0; i < 8; i++){
    int lin = tid + i * 256;
    int row = lin >> 4, c0 = (lin & 15) * 4;
    float4 v = *reinterpret_cast<const float4*>(Vb + row * DK + c0);
    t[row][c0] = v.x; t[row][c0+1] = v.y; t[row][c0+2] = v.z; t[row][c0+3] = v.w;
  }
  __syncthreads();
  __half* Hf = g_Vtf + (size_t)bh * DK * S_LEN + kt * 128;
#pragma unroll
  for (int i = 0; i < 4; i++){
    int lin = tid + i * 256;            // 1024 8-elem segments
    int d = lin >> 4, kd0 = (lin & 15) * 8;
    uint32_t w[4];
#pragma unroll
    for (int m = 0; m < 4; m++){
      int ka = kd0 + 2*m, kb = ka + 1;
      int sa = (ka & 112) | vperm(ka & 15);
      int sb = (kb & 112) | vperm(kb & 15);
      w[m] = pack_h2(t[sa][d], t[sb][d]);
    }
    *reinterpret_cast<uint4*>(Hf + (size_t)d * S_LEN + kd0) = make_uint4(w[0],w[1],w[2],w[3]);
  }
}

// ---------------------------------------------------------------------------
// k1: fused attention, 8 warps x 16 rows, 3 CTAs/SM.
// Phase A: S -> exp (unnormalized) -> l accum + PV accum (interleaved);
//          then O = O' / l written immediately.
// Phase B: S -> exp -> normalize -> coalesced STG.128 W only.
// ---------------------------------------------------------------------------
__global__ __launch_bounds__(256, 3) void k1_attn(
    float* __restrict__ Og, float* __restrict__ Wg)
{
  __shared__ alignas(16) char sm[SMEM_TOT];
  int tid = threadIdx.x, wid = tid >> 5, lane = tid & 31;
  int gr = lane >> 2, tig = lane & 3;
  int qt = blockIdx.x, bh = blockIdx.y;
  int rbase = wid * 16;

  const __half* Kb  = g_Kf  + (size_t)bh * S_LEN * DK;
  const __half* Vtb = g_Vtf + (size_t)bh * DK * S_LEN;

  // Q fragments (held in registers for both phases)
  copy_tile(g_Qf + ((size_t)bh * S_LEN + qt * 128) * DK, sm, K_OFF, tid);
  __syncthreads();
  uint32_t aq[4][4];
#pragma unroll
  for (int ks = 0; ks < 4; ks++) lda(aq[ks], sm, K_OFF, rbase, ks, gr, tig);
  __syncthreads();

  // ---------------- Phase A: l + unnormalized PV ----------------
  float oacc[8][4];
#pragma unroll
  for (int i = 0; i < 8; i++)
#pragma unroll
    for (int j = 0; j < 4; j++) oacc[i][j] = 0.f;
  float rlo = 0.f, rhi = 0.f;

  for (int kt = 0; kt < NKT; kt++){
    copy_tile(Kb + (size_t)kt * 128 * DK, sm, K_OFF, tid);
    load_v(Vtb + (size_t)kt * 128, sm, tid);
    __syncthreads();
#pragma unroll
    for (int j = 0; j < 8; j++){          // k16 chunk = n8 pair (2j, 2j+1)
      float a0[4] = {0,0,0,0}, a1[4] = {0,0,0,0};
#pragma unroll
      for (int ks = 0; ks < 4; ks++){
        uint32_t b0[2], b1[2];
        ldb(b0, sm, K_OFF, 144, 2*j,   ks, gr, tig);
        ldb(b1, sm, K_OFF, 144, 2*j+1, ks, gr, tig);
        mma_h(a0, aq[ks], b0);
        mma_h(a1, aq[ks], b1);
      }
      float p00 = __expf(a0[0]*0.125f), p01 = __expf(a0[1]*0.125f);
      float p02 = __expf(a0[2]*0.125f), p03 = __expf(a0[3]*0.125f);
      float p10 = __expf(a1[0]*0.125f), p11 = __expf(a1[1]*0.125f);
      float p12 = __expf(a1[2]*0.125f), p13 = __expf(a1[3]*0.125f);
      rlo += p00 + p01 + p10 + p11;
      rhi += p02 + p03 + p12 + p13;
      // PV A-fragment for this chunk (slot order matches permuted V)
      uint32_t pf[4];
      pf[0] = pack_h2(p00, p01);
      pf[1] = pack_h2(p02, p03);
      pf[2] = pack_h2(p10, p11);
      pf[3] = pack_h2(p12, p13);
#pragma unroll
      for (int dt = 0; dt < 8; dt++){
        uint32_t b[2];
        ldb(b, sm, V_OFF, 272, dt, j, gr, tig);
        mma_h(oacc[dt], pf, b);
      }
    }
    __syncthreads();
  }
  rlo += __shfl_xor_sync(0xFFFFFFFFu, rlo, 1);
  rlo += __shfl_xor_sync(0xFFFFFFFFu, rlo, 2);
  rhi += __shfl_xor_sync(0xFFFFFFFFu, rhi, 1);
  rhi += __shfl_xor_sync(0xFFFFFFFFu, rhi, 2);
  const float il_lo = 1.f / rlo, il_hi = 1.f / rhi;

  // Write O = O' / l now, freeing oacc for phase B.
  int row_lo = qt * 128 + rbase + gr;
  {
    float* Ob = Og + ((size_t)bh * S_LEN + row_lo) * DK;
#pragma unroll
    for (int dt = 0; dt < 8; dt++){
      int col = dt * 8 + 2 * tig;
      __stcs(reinterpret_cast<float2*>(Ob + col),
             make_float2(oacc[dt][0] * il_lo, oacc[dt][1] * il_lo));
      __stcs(reinterpret_cast<float2*>(Ob + 8 * DK + col),
             make_float2(oacc[dt][2] * il_hi, oacc[dt][3] * il_hi));
    }
  }

  // ---------------- Phase B: W only ----------------
  float* Wlo = Wg + (size_t)(bh * S_LEN + row_lo) * S_LEN;
  float* Whi = Wlo + (size_t)8 * S_LEN;

  for (int kt = 0; kt < NKT; kt++){
    copy_tile(Kb + (size_t)kt * 128 * DK, sm, K_OFF, tid);
    __syncthreads();
#pragma unroll
    for (int j = 0; j < 8; j++){
      float a0[4] = {0,0,0,0}, a1[4] = {0,0,0,0};
#pragma unroll
      for (int ks = 0; ks < 4; ks++){
        uint32_t b0[2], b1[2];
        ldb(b0, sm, K_OFF, 144, 2*j,   ks, gr, tig);
        ldb(b1, sm, K_OFF, 144, 2*j+1, ks, gr, tig);
        mma_h(a0, aq[ks], b0);
        mma_h(a1, aq[ks], b1);
      }
      float p00 = __expf(a0[0]*0.125f) * il_lo, p01 = __expf(a0[1]*0.125f) * il_lo;
      float p02 = __expf(a0[2]*0.125f) * il_hi, p03 = __expf(a0[3]*0.125f) * il_hi;
      float p10 = __expf(a1[0]*0.125f) * il_lo, p11 = __expf(a1[1]*0.125f) * il_lo;
      float p12 = __expf(a1[2]*0.125f) * il_hi, p13 = __expf(a1[3]*0.125f) * il_hi;
      // Coalesced W store (K-row permutation -> 4 consecutive original cols)
      int col = (kt * 128 + j * 16) + tig * 4;
      __stcs(reinterpret_cast<float4*>(Wlo + col), make_float4(p00, p01, p10, p11));
      __stcs(reinterpret_cast<float4*>(Whi + col), make_float4(p02, p03, p12, p13));
    }
    __syncthreads();
  }
}

// ---------------------------------------------------------------------------
extern "C" void kernel_launch(void* const* d_in, const int* in_sizes, int n_in,
                              void* d_out, int out_size)
{
  const float* Q = (const float*)d_in[0];
  const float* K = (const float*)d_in[1];
  const float* V = (const float*)d_in[2];
  float* Out = (float*)d_out;
  float* W   = Out + (size_t)BH * S_LEN * DK;

  k0_prep<<<dim3(NKT, BH), 256>>>(Q, K, V);
  k1_attn<<<dim3(NQT, BH), 256>>>(Out, W);
}

// round 16
// speedup vs baseline: 1.2795x; 1.2795x over previous
#include <cuda_runtime.h>
#include <cuda_fp16.h>
#include <cstdint>

#define S_LEN 2048
#define DK    64
#define BH    32
#define NKT   16

// smem overlay (36864 B total, 2 CTAs/SM):
//   Q super-tile [256][72] fp16 (144B rows)  -- prologue only
//   then K tile [128][72] at 0, V tile [64][136] at 18432
#define K_OFF 0
#define V_OFF 18432
#define SMEM_TOT 36864

__device__ __half g_Qf[(size_t)BH * S_LEN * DK];
__device__ __half g_Kf[(size_t)BH * S_LEN * DK];   // rows permuted within 16-groups
__device__ __half g_Vtf[(size_t)BH * DK * S_LEN];  // [bh][d][k], k permuted likewise

// slot -> original row (within a 16-group)
__device__ __forceinline__ int vperm(int o){ return ((o & 6) << 1) | ((o >> 3) << 1) | (o & 1); }
// original row -> slot (inverse)
__device__ __forceinline__ int kperm(int r){ return ((r & 2) << 2) | ((r >> 2) << 1) | (r & 1); }

// ---------------- helpers ----------------
__device__ __forceinline__ uint32_t pack_h2(float x, float y){
  __half2 t = __floats2half2_rn(x, y);
  return reinterpret_cast<uint32_t&>(t);
}

// D += A * B  (m16n8k16, fp16 in, fp32 accum)
__device__ __forceinline__ void mma_h(float* d, const uint32_t a[4], const uint32_t b[2]){
  asm volatile("mma.sync.aligned.m16n8k16.row.col.f32.f16.f16.f32 "
    "{%0,%1,%2,%3}, {%4,%5,%6,%7}, {%8,%9}, {%0,%1,%2,%3};"
    : "+f"(d[0]), "+f"(d[1]), "+f"(d[2]), "+f"(d[3])
    : "r"(a[0]), "r"(a[1]), "r"(a[2]), "r"(a[3]), "r"(b[0]), "r"(b[1]));
}

// Copy a 128x64 fp16 tile (gmem row-major) into padded smem [128][72]. 256 threads.
__device__ __forceinline__ void copy_tile(const __half* __restrict__ src,
                                          char* sm, int off, int tid){
#pragma unroll
  for (int j = 0; j < 4; j++){
    int f = tid + j * 256;              // uint4 index, 1024 total
    int row = f >> 3, c = (f & 7);
    uint4 v = *reinterpret_cast<const uint4*>(src + (size_t)row * DK + c * 8);
    *reinterpret_cast<uint4*>(sm + off + row * 144 + c * 16) = v;
  }
}

// Load 64x128 fp16 tile (V^T, row stride S_LEN in gmem) -> smem [64][136]. 256 threads.
__device__ __forceinline__ void load_v(const __half* __restrict__ vt,
                                       char* sm, int tid){
#pragma unroll
  for (int j = 0; j < 4; j++){
    int f = tid + j * 256;              // uint4 index, 1024 total
    int row = f >> 4, c = (f & 15) << 3;
    uint4 a = *reinterpret_cast<const uint4*>(vt + (size_t)row * S_LEN + c);
    *reinterpret_cast<uint4*>(sm + V_OFF + row * 272 + c * 2) = a;
  }
}

// A fragment (m16k16) from padded smem.
__device__ __forceinline__ void lda(uint32_t a[4], const char* sm, int base,
                                    int row0, int ks, int gr, int tig){
  int off = (row0 + gr) * 144 + (ks * 16 + 2 * tig) * 2;
  a[0] = *reinterpret_cast<const uint32_t*>(sm + base + off);
  a[1] = *reinterpret_cast<const uint32_t*>(sm + base + off + 8 * 144);
  a[2] = *reinterpret_cast<const uint32_t*>(sm + base + off + 16);
  a[3] = *reinterpret_cast<const uint32_t*>(sm + base + off + 8 * 144 + 16);
}

// B fragment (k16n8, col-major): rows of smem are the n dimension.
__device__ __forceinline__ void ldb(uint32_t b[2], const char* sm, int base,
                                    int rstride, int n8, int ks, int gr, int tig){
  int off = (n8 * 8 + gr) * rstride + (ks * 16 + 2 * tig) * 2;
  b[0] = *reinterpret_cast<const uint32_t*>(sm + base + off);
  b[1] = *reinterpret_cast<const uint32_t*>(sm + base + off + 16);
}

// ---------------------------------------------------------------------------
// k0: convert Q, K (K rows permuted) and V (transposed + k-permuted) to fp16
// ---------------------------------------------------------------------------
__global__ __launch_bounds__(256) void k0_prep(
    const float* __restrict__ Qg, const float* __restrict__ Kg,
    const float* __restrict__ Vg)
{
  __shared__ float t[128][65];
  int kt = blockIdx.x, bh = blockIdx.y, tid = threadIdx.x;
  size_t base = ((size_t)bh * S_LEN + kt * 128) * DK;

#pragma unroll
  for (int i = 0; i < 4; i++){
    int f = tid + i * 256;              // 8-float segment, 1024 total
    int row = f >> 3, c0 = (f & 7) * 8;
    size_t oq = base + (size_t)row * DK + c0;
    int prow = (row & 112) | kperm(row & 15);
    size_t ok = base + (size_t)prow * DK + c0;
    const float4* qp = reinterpret_cast<const float4*>(Qg + oq);
    const float4* kp = reinterpret_cast<const float4*>(Kg + oq);
    float4 q0 = qp[0], q1 = qp[1], k0 = kp[0], k1 = kp[1];
    *reinterpret_cast<uint4*>(g_Qf + oq) =
      make_uint4(pack_h2(q0.x,q0.y), pack_h2(q0.z,q0.w),
                 pack_h2(q1.x,q1.y), pack_h2(q1.z,q1.w));
    *reinterpret_cast<uint4*>(g_Kf + ok) =
      make_uint4(pack_h2(k0.x,k0.y), pack_h2(k0.z,k0.w),
                 pack_h2(k1.x,k1.y), pack_h2(k1.z,k1.w));
  }

  // V transpose through smem, then write with permuted k (slot kd holds orig k = vperm)
  const float* Vb = Vg + base;
#pragma unroll
  for (int i = 0; i < 8; i++){
    int lin = tid + i * 256;
    int row = lin >> 4, c0 = (lin & 15) * 4;
    float4 v = *reinterpret_cast<const float4*>(Vb + row * DK + c0);
    t[row][c0] = v.x; t[row][c0+1] = v.y; t[row][c0+2] = v.z; t[row][c0+3] = v.w;
  }
  __syncthreads();
  __half* Hf = g_Vtf + (size_t)bh * DK * S_LEN + kt * 128;
#pragma unroll
  for (int i = 0; i < 4; i++){
    int lin = tid + i * 256;            // 1024 8-elem segments
    int d = lin >> 4, kd0 = (lin & 15) * 8;
    uint32_t w[4];
#pragma unroll
    for (int m = 0; m < 4; m++){
      int ka = kd0 + 2*m, kb = ka + 1;
      int sa = (ka & 112) | vperm(ka & 15);
      int sb = (kb & 112) | vperm(kb & 15);
      w[m] = pack_h2(t[sa][d], t[sb][d]);
    }
    *reinterpret_cast<uint4*>(Hf + (size_t)d * S_LEN + kd0) = make_uint4(w[0],w[1],w[2],w[3]);
  }
}

// ---------------------------------------------------------------------------
// k1: fused attention, 256-row q-super-tile per CTA, 8 warps x m32.
// Phase A: l only (R14 discipline). Phase B: S -> W (coalesced) -> PV per chunk.
// Total LDS traffic across the grid halves vs m16 (half the warps re-read tiles).
// ---------------------------------------------------------------------------
__global__ __launch_bounds__(256, 2) void k1_attn(
    float* __restrict__ Og, float* __restrict__ Wg)
{
  __shared__ alignas(16) char sm[SMEM_TOT];
  int tid = threadIdx.x, wid = tid >> 5, lane = tid & 31;
  int gr = lane >> 2, tig = lane & 3;
  int qt = blockIdx.x, bh = blockIdx.y;
  int rbase = wid * 32;                  // 8 warps x 32 rows = 256-row super-tile

  const __half* Kb  = g_Kf  + (size_t)bh * S_LEN * DK;
  const __half* Vtb = g_Vtf + (size_t)bh * DK * S_LEN;

  // Prologue: Q super-tile (256x64) -> smem, extract both m16 fragment sets.
  {
    const __half* Qb = g_Qf + ((size_t)bh * S_LEN + qt * 256) * DK;
#pragma unroll
    for (int j = 0; j < 8; j++){
      int f = tid + j * 256;            // uint4 index, 2048 total
      int row = f >> 3, c = (f & 7);
      uint4 v = *reinterpret_cast<const uint4*>(Qb + (size_t)row * DK + c * 8);
      *reinterpret_cast<uint4*>(sm + row * 144 + c * 16) = v;
    }
  }
  __syncthreads();
  uint32_t aq[2][4][4];
#pragma unroll
  for (int mt = 0; mt < 2; mt++)
#pragma unroll
    for (int ks = 0; ks < 4; ks++)
      lda(aq[mt][ks], sm, 0, rbase + mt * 16, ks, gr, tig);
  __syncthreads();

  // ---------------- Phase A: row sums only ----------------
  float rs[4] = {0.f, 0.f, 0.f, 0.f};
  for (int kt = 0; kt < NKT; kt++){
    copy_tile(Kb + (size_t)kt * 128 * DK, sm, K_OFF, tid);
    __syncthreads();
#pragma unroll
    for (int j = 0; j < 8; j++){        // n8 pair (2j, 2j+1)
      float s0[8] = {0,0,0,0,0,0,0,0}, s1[8] = {0,0,0,0,0,0,0,0};
#pragma unroll
      for (int ks = 0; ks < 4; ks++){
        uint32_t b0[2], b1[2];
        ldb(b0, sm, K_OFF, 144, 2*j,   ks, gr, tig);
        ldb(b1, sm, K_OFF, 144, 2*j+1, ks, gr, tig);
        mma_h(s0,   aq[0][ks], b0); mma_h(s0+4, aq[0][ks], b1);
        mma_h(s1,   aq[1][ks], b0); mma_h(s1+4, aq[1][ks], b1);
      }
      rs[0] += __expf(s0[0]*0.125f) + __expf(s0[1]*0.125f) + __expf(s0[4]*0.125f) + __expf(s0[5]*0.125f);
      rs[1] += __expf(s0[2]*0.125f) + __expf(s0[3]*0.125f) + __expf(s0[6]*0.125f) + __expf(s0[7]*0.125f);
      rs[2] += __expf(s1[0]*0.125f) + __expf(s1[1]*0.125f) + __expf(s1[4]*0.125f) + __expf(s1[5]*0.125f);
      rs[3] += __expf(s1[2]*0.125f) + __expf(s1[3]*0.125f) + __expf(s1[6]*0.125f) + __expf(s1[7]*0.125f);
    }
    __syncthreads();
  }
  float il[4];
#pragma unroll
  for (int i = 0; i < 4; i++){
    rs[i] += __shfl_xor_sync(0xFFFFFFFFu, rs[i], 1);
    rs[i] += __shfl_xor_sync(0xFFFFFFFFu, rs[i], 2);
    il[i] = 1.f / rs[i];
  }

  // ---------------- Phase B: S, W, PV ----------------
  float oacc0[8][4], oacc1[8][4];
#pragma unroll
  for (int i = 0; i < 8; i++)
#pragma unroll
    for (int jj = 0; jj < 4; jj++){ oacc0[i][jj] = 0.f; oacc1[i][jj] = 0.f; }

  size_t wrow = (size_t)(bh * S_LEN + qt * 256 + rbase + gr);
  float* W0 = Wg + wrow * S_LEN;        // rows +0, +8 (mt0); +16, +24 (mt1)

  for (int kt = 0; kt < NKT; kt++){
    copy_tile(Kb + (size_t)kt * 128 * DK, sm, K_OFF, tid);
    load_v(Vtb + (size_t)kt * 128, sm, tid);
    __syncthreads();

#pragma unroll
    for (int j = 0; j < 8; j++){        // k16 chunk = n8 pair (2j, 2j+1)
      float s0[8] = {0,0,0,0,0,0,0,0}, s1[8] = {0,0,0,0,0,0,0,0};
#pragma unroll
      for (int ks = 0; ks < 4; ks++){
        uint32_t b0[2], b1[2];
        ldb(b0, sm, K_OFF, 144, 2*j,   ks, gr, tig);
        ldb(b1, sm, K_OFF, 144, 2*j+1, ks, gr, tig);
        mma_h(s0,   aq[0][ks], b0); mma_h(s0+4, aq[0][ks], b1);
        mma_h(s1,   aq[1][ks], b0); mma_h(s1+4, aq[1][ks], b1);
      }
      // exp + normalize. mt0 rows: {0,1,4,5}->gr (il0), {2,3,6,7}->gr+8 (il1); mt1: il2/il3.
      float p00 = __expf(s0[0]*0.125f)*il[0], p01 = __expf(s0[1]*0.125f)*il[0];
      float p02 = __expf(s0[2]*0.125f)*il[1], p03 = __expf(s0[3]*0.125f)*il[1];
      float p10 = __expf(s0[4]*0.125f)*il[0], p11 = __expf(s0[5]*0.125f)*il[0];
      float p12 = __expf(s0[6]*0.125f)*il[1], p13 = __expf(s0[7]*0.125f)*il[1];
      float q00 = __expf(s1[0]*0.125f)*il[2], q01 = __expf(s1[1]*0.125f)*il[2];
      float q02 = __expf(s1[2]*0.125f)*il[3], q03 = __expf(s1[3]*0.125f)*il[3];
      float q10 = __expf(s1[4]*0.125f)*il[2], q11 = __expf(s1[5]*0.125f)*il[2];
      float q12 = __expf(s1[6]*0.125f)*il[3], q13 = __expf(s1[7]*0.125f)*il[3];

      // Coalesced W stores (K-row permutation -> 4 consecutive original cols)
      int col = (kt * 128 + j * 16) + tig * 4;
      __stcs(reinterpret_cast<float4*>(W0 + col),                      make_float4(p00, p01, p10, p11));
      __stcs(reinterpret_cast<float4*>(W0 + (size_t) 8 * S_LEN + col), make_float4(p02, p03, p12, p13));
      __stcs(reinterpret_cast<float4*>(W0 + (size_t)16 * S_LEN + col), make_float4(q00, q01, q10, q11));
      __stcs(reinterpret_cast<float4*>(W0 + (size_t)24 * S_LEN + col), make_float4(q02, q03, q12, q13));

      // PV A-fragments for this chunk (slot order matches permuted V)
      uint32_t pf0[4], pf1[4];
      pf0[0] = pack_h2(p00, p01); pf0[1] = pack_h2(p02, p03);
      pf0[2] = pack_h2(p10, p11); pf0[3] = pack_h2(p12, p13);
      pf1[0] = pack_h2(q00, q01); pf1[1] = pack_h2(q02, q03);
      pf1[2] = pack_h2(q10, q11); pf1[3] = pack_h2(q12, q13);

      // PV: O += P_chunk * V_chunk (V B-fragment shared by both m-tiles)
#pragma unroll
      for (int dt = 0; dt < 8; dt++){
        uint32_t b[2];
        ldb(b, sm, V_OFF, 272, dt, j, gr, tig);
        mma_h(oacc0[dt], pf0, b);
        mma_h(oacc1[dt], pf1, b);
      }
    }
    __syncthreads();
  }

  float* Ob = Og + wrow * DK;           // rows +0, +8, +16, +24
#pragma unroll
  for (int dt = 0; dt < 8; dt++){
    int col = dt * 8 + 2 * tig;
    __stcs(reinterpret_cast<float2*>(Ob + col),                    make_float2(oacc0[dt][0], oacc0[dt][1]));
    __stcs(reinterpret_cast<float2*>(Ob + (size_t) 8 * DK + col),  make_float2(oacc0[dt][2], oacc0[dt][3]));
    __stcs(reinterpret_cast<float2*>(Ob + (size_t)16 * DK + col),  make_float2(oacc1[dt][0], oacc1[dt][1]));
    __stcs(reinterpret_cast<float2*>(Ob + (size_t)24 * DK + col),  make_float2(oacc1[dt][2], oacc1[dt][3]));
  }
}

// ---------------------------------------------------------------------------
extern "C" void kernel_launch(void* const* d_in, const int* in_sizes, int n_in,
                              void* d_out, int out_size)
{
  const float* Q = (const float*)d_in[0];
  const float* K = (const float*)d_in[1];
  const float* V = (const float*)d_in[2];
  float* Out = (float*)d_out;
  float* W   = Out + (size_t)BH * S_LEN * DK;

  k0_prep<<<dim3(NKT, BH), 256>>>(Q, K, V);
  k1_attn<<<dim3(8, BH), 256>>>(Out, W);   // 256-row super-tiles: 8 x 32 CTAs
}

// round 17
// speedup vs baseline: 1.3009x; 1.0168x over previous
#include <cuda_runtime.h>
#include <cuda_fp16.h>
#include <cstdint>

#define S_LEN 2048
#define DK    64
#define BH    32
#define NKT   16

// Dynamic smem layout (71680 B, 2 CTAs/SM):
//   prologue: Q super-tile [256][72] fp16 (144B rows) at 0   (overlaps K bufs)
//   pipeline: K bufs [128][72]x2 at 0/18432; V bufs [64][136]x2 at 36864/54272
#define KB0 0
#define KB1 18432
#define VB0 36864
#define VB1 54272
#define SMEM_TOT 71680

__device__ __half g_Qf[(size_t)BH * S_LEN * DK];
__device__ __half g_Kf[(size_t)BH * S_LEN * DK];   // rows permuted within 16-groups
__device__ __half g_Vtf[(size_t)BH * DK * S_LEN];  // [bh][d][k], k permuted likewise

// slot -> original row (within a 16-group)
__device__ __forceinline__ int vperm(int o){ return ((o & 6) << 1) | ((o >> 3) << 1) | (o & 1); }
// original row -> slot (inverse)
__device__ __forceinline__ int kperm(int r){ return ((r & 2) << 2) | ((r >> 2) << 1) | (r & 1); }

// ---------------- helpers ----------------
__device__ __forceinline__ uint32_t pack_h2(float x, float y){
  __half2 t = __floats2half2_rn(x, y);
  return reinterpret_cast<uint32_t&>(t);
}

__device__ __forceinline__ void mma_h(float* d, const uint32_t a[4], const uint32_t b[2]){
  asm volatile("mma.sync.aligned.m16n8k16.row.col.f32.f16.f16.f32 "
    "{%0,%1,%2,%3}, {%4,%5,%6,%7}, {%8,%9}, {%0,%1,%2,%3};"
    : "+f"(d[0]), "+f"(d[1]), "+f"(d[2]), "+f"(d[3])
    : "r"(a[0]), "r"(a[1]), "r"(a[2]), "r"(a[3]), "r"(b[0]), "r"(b[1]));
}

// 16B async copy gmem -> smem
__device__ __forceinline__ void cp16(uint32_t smaddr, const void* gptr){
  asm volatile("cp.async.cg.shared.global [%0], [%1], 16;" :: "r"(smaddr), "l"(gptr));
}
#define CP_COMMIT() asm volatile("cp.async.commit_group;" ::: "memory")
#define CP_WAIT1()  asm volatile("cp.async.wait_group 1;" ::: "memory")
#define CP_WAIT0()  asm volatile("cp.async.wait_group 0;" ::: "memory")

// K tile 128x64 fp16 -> padded smem [128][72], async. 256 threads, 1024 chunks.
__device__ __forceinline__ void k_tile_async(const __half* __restrict__ src,
                                             uint32_t smb, int tid){
#pragma unroll
  for (int j = 0; j < 4; j++){
    int f = tid + j * 256;
    int row = f >> 3, c = f & 7;
    cp16(smb + row * 144 + c * 16, src + (size_t)row * DK + c * 8);
  }
}
// V tile 64x128 fp16 (row stride S_LEN) -> smem [64][136], async.
__device__ __forceinline__ void v_tile_async(const __half* __restrict__ vt,
                                             uint32_t smb, int tid){
#pragma unroll
  for (int j = 0; j < 4; j++){
    int f = tid + j * 256;
    int row = f >> 4, c = (f & 15) << 3;
    cp16(smb + row * 272 + c * 2, vt + (size_t)row * S_LEN + c);
  }
}

// A fragment (m16k16) from padded smem.
__device__ __forceinline__ void lda(uint32_t a[4], const char* sm, int base,
                                    int row0, int ks, int gr, int tig){
  int off = (row0 + gr) * 144 + (ks * 16 + 2 * tig) * 2;
  a[0] = *reinterpret_cast<const uint32_t*>(sm + base + off);
  a[1] = *reinterpret_cast<const uint32_t*>(sm + base + off + 8 * 144);
  a[2] = *reinterpret_cast<const uint32_t*>(sm + base + off + 16);
  a[3] = *reinterpret_cast<const uint32_t*>(sm + base + off + 8 * 144 + 16);
}
// B fragment (k16n8, col-major): rows of smem are the n dimension.
__device__ __forceinline__ void ldb(uint32_t b[2], const char* sm, int base,
                                    int rstride, int n8, int ks, int gr, int tig){
  int off = (n8 * 8 + gr) * rstride + (ks * 16 + 2 * tig) * 2;
  b[0] = *reinterpret_cast<const uint32_t*>(sm + base + off);
  b[1] = *reinterpret_cast<const uint32_t*>(sm + base + off + 16);
}

// ---------------------------------------------------------------------------
// k0: convert Q, K (K rows permuted) and V (transposed + k-permuted) to fp16
// ---------------------------------------------------------------------------
__global__ __launch_bounds__(256) void k0_prep(
    const float* __restrict__ Qg, const float* __restrict__ Kg,
    const float* __restrict__ Vg)
{
  __shared__ float t[128][65];
  int kt = blockIdx.x, bh = blockIdx.y, tid = threadIdx.x;
  size_t base = ((size_t)bh * S_LEN + kt * 128) * DK;

#pragma unroll
  for (int i = 0; i < 4; i++){
    int f = tid + i * 256;
    int row = f >> 3, c0 = (f & 7) * 8;
    size_t oq = base + (size_t)row * DK + c0;
    int prow = (row & 112) | kperm(row & 15);
    size_t ok = base + (size_t)prow * DK + c0;
    const float4* qp = reinterpret_cast<const float4*>(Qg + oq);
    const float4* kp = reinterpret_cast<const float4*>(Kg + oq);
    float4 q0 = qp[0], q1 = qp[1], k0 = kp[0], k1 = kp[1];
    *reinterpret_cast<uint4*>(g_Qf + oq) =
      make_uint4(pack_h2(q0.x,q0.y), pack_h2(q0.z,q0.w),
                 pack_h2(q1.x,q1.y), pack_h2(q1.z,q1.w));
    *reinterpret_cast<uint4*>(g_Kf + ok) =
      make_uint4(pack_h2(k0.x,k0.y), pack_h2(k0.z,k0.w),
                 pack_h2(k1.x,k1.y), pack_h2(k1.z,k1.w));
  }

  const float* Vb = Vg + base;
#pragma unroll
  for (int i = 0; i < 8; i++){
    int lin = tid + i * 256;
    int row = lin >> 4, c0 = (lin & 15) * 4;
    float4 v = *reinterpret_cast<const float4*>(Vb + row * DK + c0);
    t[row][c0] = v.x; t[row][c0+1] = v.y; t[row][c0+2] = v.z; t[row][c0+3] = v.w;
  }
  __syncthreads();
  __half* Hf = g_Vtf + (size_t)bh * DK * S_LEN + kt * 128;
#pragma unroll
  for (int i = 0; i < 4; i++){
    int lin = tid + i * 256;
    int d = lin >> 4, kd0 = (lin & 15) * 8;
    uint32_t w[4];
#pragma unroll
    for (int m = 0; m < 4; m++){
      int ka = kd0 + 2*m, kb = ka + 1;
      int sa = (ka & 112) | vperm(ka & 15);
      int sb = (kb & 112) | vperm(kb & 15);
      w[m] = pack_h2(t[sa][d], t[sb][d]);
    }
    *reinterpret_cast<uint4*>(Hf + (size_t)d * S_LEN + kd0) = make_uint4(w[0],w[1],w[2],w[3]);
  }
}

// ---------------------------------------------------------------------------
// k1: fused attention, 256-row q-super-tile, 8 warps x m32, cp.async pipeline.
// Phase A: l only (K double-buffered). Phase B: S -> W -> PV (K+V double-buffered).
// ---------------------------------------------------------------------------
__global__ __launch_bounds__(256, 2) void k1_attn(
    float* __restrict__ Og, float* __restrict__ Wg)
{
  extern __shared__ char smp[];
  uint32_t smb = (uint32_t)__cvta_generic_to_shared(smp);
  int tid = threadIdx.x, wid = tid >> 5, lane = tid & 31;
  int gr = lane >> 2, tig = lane & 3;
  int qt = blockIdx.x, bh = blockIdx.y;
  int rbase = wid * 32;

  const __half* Kb  = g_Kf  + (size_t)bh * S_LEN * DK;
  const __half* Vtb = g_Vtf + (size_t)bh * DK * S_LEN;

  // Prologue: Q super-tile (256x64) -> smem, extract both m16 fragment sets.
  {
    const __half* Qb = g_Qf + ((size_t)bh * S_LEN + qt * 256) * DK;
#pragma unroll
    for (int j = 0; j < 8; j++){
      int f = tid + j * 256;
      int row = f >> 3, c = f & 7;
      uint4 v = *reinterpret_cast<const uint4*>(Qb + (size_t)row * DK + c * 8);
      *reinterpret_cast<uint4*>(smp + row * 144 + c * 16) = v;
    }
  }
  __syncthreads();
  uint32_t aq[2][4][4];
#pragma unroll
  for (int mt = 0; mt < 2; mt++)
#pragma unroll
    for (int ks = 0; ks < 4; ks++)
      lda(aq[mt][ks], smp, 0, rbase + mt * 16, ks, gr, tig);
  __syncthreads();

  // ---------------- Phase A: row sums (K pipeline) ----------------
  float rs[4] = {0.f, 0.f, 0.f, 0.f};
  k_tile_async(Kb, smb + KB0, tid); CP_COMMIT();
  for (int kt = 0; kt < NKT; kt++){
    if (kt + 1 < NKT){
      k_tile_async(Kb + (size_t)(kt + 1) * 128 * DK, smb + ((kt + 1) & 1 ? KB1 : KB0), tid);
      CP_COMMIT();
      CP_WAIT1();
    } else {
      CP_WAIT0();
    }
    __syncthreads();
    int kof = (kt & 1) ? KB1 : KB0;
#pragma unroll
    for (int j = 0; j < 8; j++){
      float s0[8] = {0,0,0,0,0,0,0,0}, s1[8] = {0,0,0,0,0,0,0,0};
#pragma unroll
      for (int ks = 0; ks < 4; ks++){
        uint32_t b0[2], b1[2];
        ldb(b0, smp, kof, 144, 2*j,   ks, gr, tig);
        ldb(b1, smp, kof, 144, 2*j+1, ks, gr, tig);
        mma_h(s0,   aq[0][ks], b0); mma_h(s0+4, aq[0][ks], b1);
        mma_h(s1,   aq[1][ks], b0); mma_h(s1+4, aq[1][ks], b1);
      }
      rs[0] += __expf(s0[0]*0.125f) + __expf(s0[1]*0.125f) + __expf(s0[4]*0.125f) + __expf(s0[5]*0.125f);
      rs[1] += __expf(s0[2]*0.125f) + __expf(s0[3]*0.125f) + __expf(s0[6]*0.125f) + __expf(s0[7]*0.125f);
      rs[2] += __expf(s1[0]*0.125f) + __expf(s1[1]*0.125f) + __expf(s1[4]*0.125f) + __expf(s1[5]*0.125f);
      rs[3] += __expf(s1[2]*0.125f) + __expf(s1[3]*0.125f) + __expf(s1[6]*0.125f) + __expf(s1[7]*0.125f);
    }
    __syncthreads();
  }
  float il[4];
#pragma unroll
  for (int i = 0; i < 4; i++){
    rs[i] += __shfl_xor_sync(0xFFFFFFFFu, rs[i], 1);
    rs[i] += __shfl_xor_sync(0xFFFFFFFFu, rs[i], 2);
    il[i] = 1.f / rs[i];
  }

  // ---------------- Phase B: S, W, PV (K+V pipeline) ----------------
  float oacc0[8][4], oacc1[8][4];
#pragma unroll
  for (int i = 0; i < 8; i++)
#pragma unroll
    for (int jj = 0; jj < 4; jj++){ oacc0[i][jj] = 0.f; oacc1[i][jj] = 0.f; }

  size_t wrow = (size_t)(bh * S_LEN + qt * 256 + rbase + gr);
  float* W0 = Wg + wrow * S_LEN;

  k_tile_async(Kb, smb + KB0, tid);
  v_tile_async(Vtb, smb + VB0, tid);
  CP_COMMIT();
  for (int kt = 0; kt < NKT; kt++){
    if (kt + 1 < NKT){
      int nb = (kt + 1) & 1;
      k_tile_async(Kb + (size_t)(kt + 1) * 128 * DK, smb + (nb ? KB1 : KB0), tid);
      v_tile_async(Vtb + (size_t)(kt + 1) * 128,     smb + (nb ? VB1 : VB0), tid);
      CP_COMMIT();
      CP_WAIT1();
    } else {
      CP_WAIT0();
    }
    __syncthreads();
    int kof = (kt & 1) ? KB1 : KB0;
    int vof = (kt & 1) ? VB1 : VB0;

#pragma unroll
    for (int j = 0; j < 8; j++){
      float s0[8] = {0,0,0,0,0,0,0,0}, s1[8] = {0,0,0,0,0,0,0,0};
#pragma unroll
      for (int ks = 0; ks < 4; ks++){
        uint32_t b0[2], b1[2];
        ldb(b0, smp, kof, 144, 2*j,   ks, gr, tig);
        ldb(b1, smp, kof, 144, 2*j+1, ks, gr, tig);
        mma_h(s0,   aq[0][ks], b0); mma_h(s0+4, aq[0][ks], b1);
        mma_h(s1,   aq[1][ks], b0); mma_h(s1+4, aq[1][ks], b1);
      }
      float p00 = __expf(s0[0]*0.125f)*il[0], p01 = __expf(s0[1]*0.125f)*il[0];
      float p02 = __expf(s0[2]*0.125f)*il[1], p03 = __expf(s0[3]*0.125f)*il[1];
      float p10 = __expf(s0[4]*0.125f)*il[0], p11 = __expf(s0[5]*0.125f)*il[0];
      float p12 = __expf(s0[6]*0.125f)*il[1], p13 = __expf(s0[7]*0.125f)*il[1];
      float q00 = __expf(s1[0]*0.125f)*il[2], q01 = __expf(s1[1]*0.125f)*il[2];
      float q02 = __expf(s1[2]*0.125f)*il[3], q03 = __expf(s1[3]*0.125f)*il[3];
      float q10 = __expf(s1[4]*0.125f)*il[2], q11 = __expf(s1[5]*0.125f)*il[2];
      float q12 = __expf(s1[6]*0.125f)*il[3], q13 = __expf(s1[7]*0.125f)*il[3];

      int col = (kt * 128 + j * 16) + tig * 4;
      __stcs(reinterpret_cast<float4*>(W0 + col),                      make_float4(p00, p01, p10, p11));
      __stcs(reinterpret_cast<float4*>(W0 + (size_t) 8 * S_LEN + col), make_float4(p02, p03, p12, p13));
      __stcs(reinterpret_cast<float4*>(W0 + (size_t)16 * S_LEN + col), make_float4(q00, q01, q10, q11));
      __stcs(reinterpret_cast<float4*>(W0 + (size_t)24 * S_LEN + col), make_float4(q02, q03, q12, q13));

      uint32_t pf0[4], pf1[4];
      pf0[0] = pack_h2(p00, p01); pf0[1] = pack_h2(p02, p03);
      pf0[2] = pack_h2(p10, p11); pf0[3] = pack_h2(p12, p13);
      pf1[0] = pack_h2(q00, q01); pf1[1] = pack_h2(q02, q03);
      pf1[2] = pack_h2(q10, q11); pf1[3] = pack_h2(q12, q13);

#pragma unroll
      for (int dt = 0; dt < 8; dt++){
        uint32_t b[2];
        ldb(b, smp, vof, 272, dt, j, gr, tig);
        mma_h(oacc0[dt], pf0, b);
        mma_h(oacc1[dt], pf1, b);
      }
    }
    __syncthreads();
  }

  float* Ob = Og + wrow * DK;
#pragma unroll
  for (int dt = 0; dt < 8; dt++){
    int col = dt * 8 + 2 * tig;
    __stcs(reinterpret_cast<float2*>(Ob + col),                    make_float2(oacc0[dt][0], oacc0[dt][1]));
    __stcs(reinterpret_cast<float2*>(Ob + (size_t) 8 * DK + col),  make_float2(oacc0[dt][2], oacc0[dt][3]));
    __stcs(reinterpret_cast<float2*>(Ob + (size_t)16 * DK + col),  make_float2(oacc1[dt][0], oacc1[dt][1]));
    __stcs(reinterpret_cast<float2*>(Ob + (size_t)24 * DK + col),  make_float2(oacc1[dt][2], oacc1[dt][3]));
  }
}

// ---------------------------------------------------------------------------
extern "C" void kernel_launch(void* const* d_in, const int* in_sizes, int n_in,
                              void* d_out, int out_size)
{
  const float* Q = (const float*)d_in[0];
  const float* K = (const float*)d_in[1];
  const float* V = (const float*)d_in[2];
  float* Out = (float*)d_out;
  float* W   = Out + (size_t)BH * S_LEN * DK;

  cudaFuncSetAttribute(k1_attn, cudaFuncAttributeMaxDynamicSharedMemorySize, SMEM_TOT);
  k0_prep<<<dim3(NKT, BH), 256>>>(Q, K, V);
  k1_attn<<<dim3(8, BH), 256, SMEM_TOT>>>(Out, W);
}